// round 13
// baseline (speedup 1.0000x reference)
#include <cuda_runtime.h>

// Problem constants (fixed by the reference):
//   encoder_outputs : [B, L, D] f32   = d_in[0]
//   durations       : [B, L]    i32   = d_in[1]
//   frames_positions: [B, T, P] f32   = d_in[2]
//   input_lengths   : [B]       i32   = d_in[3]  (UNUSED by reference)
//   output          : [B, T, D+P] f32
#define BB 16
#define LL 512
#define DD 512
#define TT 4096
#define PP 4

#define DV (DD / 4)          // 128 float4 per encoder row
#define ROW_V (DV + 1)       // 129 float4 per output row (516 floats, 2064 B)
#define ROWS_PB 32           // rows (frames) per block
#define BLKS_PER_B (TT / ROWS_PB)       // 128 blocks per batch
#define BLK_F4 (ROWS_PB * ROW_V)        // 4128 float4 per block (66048 B)
#define BLK_F8 (BLK_F4 / 2)             // 2064 256-bit units per block

// 256-bit streaming store (sm_100+ PTX .v8.f32). addr must be 32B-aligned.
__device__ __forceinline__ void st_v8_cs(float4* addr, float4 a, float4 b) {
    asm volatile(
        "st.global.cs.v8.f32 [%0], {%1,%2,%3,%4,%5,%6,%7,%8};"
        :: "l"(addr),
           "f"(a.x), "f"(a.y), "f"(a.z), "f"(a.w),
           "f"(b.x), "f"(b.y), "f"(b.z), "f"(b.w)
        : "memory");
}

// ---------------------------------------------------------------------------
// Single fused kernel, round-13:
//  - Phase A: in-block warp-shuffle cumsum of the batch's 512 durations +
//    scatter of token indices for this block's 32-frame window into smem.
//  - Phase B: linear output streaming of the block's contiguous 66048-byte
//    region using 256-bit st.global.cs.v8.f32 (halves STG count and L1
//    store-wavefront insertions vs STG.128). Each f8 unit fetches its two
//    float4 halves independently (129 f4/row is odd, so an f8 may straddle
//    a row boundary / the positions-tail column).
// ---------------------------------------------------------------------------
__global__ __launch_bounds__(512) void durian_fused_kernel(
    const int*    __restrict__ dur,   // [B, L]
    const float4* __restrict__ enc,   // [B*L, 128] float4
    const float4* __restrict__ fp,    // [B*T] float4
    float4*       __restrict__ out)   // [B*T, 129] float4
{
    __shared__ int s_wsum[16];
    __shared__ int s_idx[ROWS_PB];

    const int tid   = threadIdx.x;
    const int b     = blockIdx.x >> 7;            // / BLKS_PER_B
    const int blk   = blockIdx.x & (BLKS_PER_B - 1);
    const int t0    = blk * ROWS_PB;              // first frame of this block
    const int row0g = b * TT + t0;                // first global output row

    // ---- Phase A: per-batch inclusive cumsum of durations (L=512) --------
    const int lane = tid & 31;
    const int wid  = tid >> 5;                    // 16 warps
    const int d    = dur[b * LL + tid];           // one duration per thread
    int x = d;
    #pragma unroll
    for (int o = 1; o < 32; o <<= 1) {
        int y = __shfl_up_sync(0xffffffffu, x, o);
        if (lane >= o) x += y;
    }
    if (lane == 31) s_wsum[wid] = x;
    if (tid < ROWS_PB) s_idx[tid] = -1;           // init window map
    __syncthreads();
    if (wid == 0) {
        int w = (lane < 16) ? s_wsum[lane] : 0;
        #pragma unroll
        for (int o = 1; o < 16; o <<= 1) {
            int y = __shfl_up_sync(0xffffffffu, w, o);
            if (lane >= o) w += y;
        }
        if (lane < 16) s_wsum[lane] = w;          // inclusive warp prefix
    }
    __syncthreads();

    // Token tid covers frames [end - d, end); end = inclusive cumsum.
    const int prefix = (wid == 0) ? 0 : s_wsum[wid - 1];
    const int end    = prefix + x;
    const int start  = end - d;

    // Scatter into this block's 32-frame window (disjoint ranges, no races)
    int lo = start > t0 ? start : t0;
    int hi = end < t0 + ROWS_PB ? end : t0 + ROWS_PB;
    for (int t = lo; t < hi; t++)
        s_idx[t - t0] = tid;
    __syncthreads();

    // ---- Phase B: linear 256-bit streaming of the output region ----------
    const float4* encb = enc + (size_t)b * LL * DV;
    float4* oblk = out + (size_t)row0g * ROW_V;   // 128B-aligned block base

    // Fetch one float4 of the block's flat output stream (i in [0, 4128)).
    auto fetch = [&](int i) -> float4 {
        const int row = i / ROW_V;                // local frame 0..31
        const int col = i - row * ROW_V;          // 0..128
        if (col == DV)
            return fp[row0g + row];               // positions tail
        const int idx = s_idx[row];
        if (idx >= 0)
            return encb[(size_t)idx * DV + col];
        return make_float4(0.f, 0.f, 0.f, 0.f);
    };

    // 2064 f8 = 4 * 512 + 16: 4 full sweeps + a 16-thread tail.
    #pragma unroll
    for (int it = 0; it < 4; it++) {
        const int j  = tid + it * 512;            // f8 index in block
        float4 v0 = fetch(2 * j);
        float4 v1 = fetch(2 * j + 1);
        st_v8_cs(&oblk[2 * j], v0, v1);
    }
    if (tid < BLK_F8 - 4 * 512) {                 // tail: j in [2048, 2064)
        const int j  = tid + 4 * 512;
        float4 v0 = fetch(2 * j);
        float4 v1 = fetch(2 * j + 1);
        st_v8_cs(&oblk[2 * j], v0, v1);
    }
}

extern "C" void kernel_launch(void* const* d_in, const int* in_sizes, int n_in,
                              void* d_out, int out_size) {
    const float* enc = (const float*)d_in[0];
    const int*   dur = (const int*)  d_in[1];
    const float* fp  = (const float*)d_in[2];
    // d_in[3] = input_lengths: unused by the reference.
    (void)in_sizes; (void)n_in; (void)out_size;

    durian_fused_kernel<<<BB * BLKS_PER_B, 512>>>(
        dur,
        (const float4*)enc,
        (const float4*)fp,
        (float4*)d_out);
}

// round 14
// speedup vs baseline: 1.1251x; 1.1251x over previous
#include <cuda_runtime.h>

// Problem constants (fixed by the reference):
//   encoder_outputs : [B, L, D] f32   = d_in[0]
//   durations       : [B, L]    i32   = d_in[1]
//   frames_positions: [B, T, P] f32   = d_in[2]
//   input_lengths   : [B]       i32   = d_in[3]  (UNUSED by reference)
//   output          : [B, T, D+P] f32
#define BB 16
#define LL 512
#define DD 512
#define TT 4096
#define PP 4

#define DV (DD / 4)          // 128 float4 per encoder row
#define ROW_V (DV + 1)       // 129 float4 per output row (516 floats, 2064 B)
#define RPG 8                // rows per 128-lane group (ILP batch)
#define ROWS_PB 32           // rows per block (4 groups * RPG)
#define BLKS_PER_B (TT / ROWS_PB)   // 128 blocks per batch

// ---------------------------------------------------------------------------
// Single fused kernel = round-9 champion (25.06us) + gather dedup.
// Phase A: in-block warp-shuffle cumsum of the batch's 512 durations +
//          scatter of token indices for this block's 32-frame window to smem.
// Phase B: 8-row ILP gather + __stcs streaming row stores (round-9 body),
//          with one change: consecutive rows sharing a token (mean duration
//          3.5 -> ~2-3 distinct tokens per 8-row group) REUSE the loaded
//          register instead of re-issuing an identical LDG.128. idx[] is
//          uniform across the 128-lane group, so the select is warp-uniform.
//          Cuts enc LDG count ~2.5-3x, attacking the top gauge (L1 55%).
// ---------------------------------------------------------------------------
__global__ __launch_bounds__(512) void durian_fused_kernel(
    const int*    __restrict__ dur,   // [B, L]
    const float4* __restrict__ enc,   // [B*L, 128] float4
    const float4* __restrict__ fp,    // [B*T] float4
    float4*       __restrict__ out)   // [B*T, 129] float4
{
    __shared__ int s_wsum[16];
    __shared__ int s_idx[ROWS_PB];

    const int tid   = threadIdx.x;
    const int b     = blockIdx.x >> 7;            // / BLKS_PER_B
    const int blk   = blockIdx.x & (BLKS_PER_B - 1);
    const int t0    = blk * ROWS_PB;              // first frame of this block
    const int row0g = b * TT + t0;                // first global output row

    // ---- Phase A: per-batch inclusive cumsum of durations (L=512) --------
    const int lane = tid & 31;
    const int wid  = tid >> 5;                    // 16 warps
    const int d    = dur[b * LL + tid];           // one duration per thread
    int x = d;
    #pragma unroll
    for (int o = 1; o < 32; o <<= 1) {
        int y = __shfl_up_sync(0xffffffffu, x, o);
        if (lane >= o) x += y;
    }
    if (lane == 31) s_wsum[wid] = x;
    if (tid < ROWS_PB) s_idx[tid] = -1;           // init window map
    __syncthreads();
    if (wid == 0) {
        int w = (lane < 16) ? s_wsum[lane] : 0;
        #pragma unroll
        for (int o = 1; o < 16; o <<= 1) {
            int y = __shfl_up_sync(0xffffffffu, w, o);
            if (lane >= o) w += y;
        }
        if (lane < 16) s_wsum[lane] = w;          // inclusive warp prefix
    }
    __syncthreads();

    // Token tid covers frames [end - d, end); end = inclusive cumsum.
    const int prefix = (wid == 0) ? 0 : s_wsum[wid - 1];
    const int end    = prefix + x;
    const int start  = end - d;

    // Scatter into this block's 32-frame window (disjoint ranges, no races)
    int lo = start > t0 ? start : t0;
    int hi = end < t0 + ROWS_PB ? end : t0 + ROWS_PB;
    for (int t = lo; t < hi; t++)
        s_idx[t - t0] = tid;
    __syncthreads();

    // ---- Phase B: expansion + concat (round-9 body + dedup) --------------
    const int grp   = tid >> 7;                   // 0..3 group within block
    const int flane = tid & 127;                  // float4 column within row
    const int lrow0 = grp * RPG;                  // local first row of group
    const int rowg  = row0g + lrow0;              // first global row of group

    int idx[RPG];
    #pragma unroll
    for (int r = 0; r < RPG; r++)
        idx[r] = s_idx[lrow0 + r];                // LDS broadcast

    // Positions tail value (independent load, overlaps the gathers)
    float4 tail;
    if (flane < RPG)
        tail = fp[rowg + flane];

    const float4* encb = enc + (size_t)b * LL * DV;
    float4 v[RPG];
    #pragma unroll
    for (int r = 0; r < RPG; r++) {
        if (r > 0 && idx[r] == idx[r - 1]) {
            v[r] = v[r - 1];                      // same token: reuse register
        } else if (idx[r] >= 0) {
            v[r] = encb[(size_t)idx[r] * DV + flane];
        } else {
            v[r] = make_float4(0.f, 0.f, 0.f, 0.f);
        }
    }

    // 8 streaming stores (write-once output; evict-first keeps L2 stable
    // across graph replays — default policy measured +5us churn in R10)
    #pragma unroll
    for (int r = 0; r < RPG; r++)
        __stcs(&out[(size_t)(rowg + r) * ROW_V + flane], v[r]);

    // Positions tail: lanes 0..7 of each group handle one row each
    if (flane < RPG)
        __stcs(&out[(size_t)(rowg + flane) * ROW_V + DV], tail);
}

extern "C" void kernel_launch(void* const* d_in, const int* in_sizes, int n_in,
                              void* d_out, int out_size) {
    const float* enc = (const float*)d_in[0];
    const int*   dur = (const int*)  d_in[1];
    const float* fp  = (const float*)d_in[2];
    // d_in[3] = input_lengths: unused by the reference.
    (void)in_sizes; (void)n_in; (void)out_size;

    durian_fused_kernel<<<BB * BLKS_PER_B, 512>>>(
        dur,
        (const float4*)enc,
        (const float4*)fp,
        (float4*)d_out);
}